// round 10
// baseline (speedup 1.0000x reference)
#include <cuda_runtime.h>
#include <cuda_bf16.h>
#include <math.h>
#include <stdint.h>

#define BATCH 4096
#define EMB 256
#define HID 256
#define FREQ 96
#define CHAN 16
#define OC 10
#define KT 5

#define OFF_COEFS 0
#define N_COEFS   (BATCH * 5 * 96 * 2)
#define OFF_ALPHA (N_COEFS)
#define N_ALPHA   (BATCH)
#define OFF_STATE (OFF_ALPHA + N_ALPHA)
#define N_STATE   (BATCH * 2 * HID)
#define OFF_BUF   (OFF_STATE + N_STATE)
#define N_BUF     (BATCH * 4 * FREQ * CHAN)

__device__ float g_xin[BATCH * HID];
__device__ float g_c[BATCH * HID];

#define MMA_TF32(d, a, b0v, b1v) \
  asm volatile("mma.sync.aligned.m16n8k8.row.col.f32.tf32.tf32.f32 " \
      "{%0,%1,%2,%3}, {%4,%5,%6,%7}, {%8,%9}, {%0,%1,%2,%3};" \
      : "+f"((d)[0]), "+f"((d)[1]), "+f"((d)[2]), "+f"((d)[3]) \
      : "r"((a)[0]), "r"((a)[1]), "r"((a)[2]), "r"((a)[3]), \
        "r"(b0v), "r"(b1v))

#define LDSM4(r0, r1, r2, r3, a) \
  asm volatile("ldmatrix.sync.aligned.m8n8.x4.shared.b16 {%0,%1,%2,%3}, [%4];" \
      : "=r"(r0), "=r"(r1), "=r"(r2), "=r"(r3) : "r"(a))

#define CP16(dst_u32, src_ptr) \
  asm volatile("cp.async.ca.shared.global [%0], [%1], 16;" :: "r"(dst_u32), "l"(src_ptr))
#define CP_COMMIT() asm volatile("cp.async.commit_group;")
#define CP_WAIT1()  asm volatile("cp.async.wait_group 1;")

// ---------------------------------------------------------------------------
// x_in = relu(grouped_linear(emb, w_in))
// ---------------------------------------------------------------------------
__global__ __launch_bounds__(256) void xin_kernel(
    const float* __restrict__ emb, const float* __restrict__ w_in,
    float* __restrict__ xout)
{
    __shared__ float sE[8][EMB];
    int b0 = blockIdx.x * 8;
    int tid = threadIdx.x;
    for (int idx = tid; idx < 8 * EMB; idx += 256) {
        int r = idx >> 8, col = idx & 255;
        sE[r][col] = emb[(b0 + r) * EMB + col];
    }
    __syncthreads();
    int j = tid;
    int g = j >> 5, jo = j & 31;
    float acc[8] = {0.f,0.f,0.f,0.f,0.f,0.f,0.f,0.f};
    const float* w = w_in + g * (32 * 32) + jo;
    #pragma unroll 8
    for (int i = 0; i < 32; i++) {
        float wv = w[i * 32];
        #pragma unroll
        for (int r = 0; r < 8; r++)
            acc[r] = fmaf(sE[r][(g << 5) + i], wv, acc[r]);
    }
    #pragma unroll
    for (int r = 0; r < 8; r++)
        xout[(b0 + r) * HID + j] = fmaxf(acc[r], 0.f);
}

// ---------------------------------------------------------------------------
// Fused GRU cell, tf32 mma + ldmatrix. CTA tile 64 x 32 for 3 CTAs/SM.
// smem stage (floats): X 64x20 (@0), H 64x20 (@1280), WT 6x32x20 (@2560).
// 8 warps = 4 warp_m (m16) x 2 warp_n (n16). grid (64, 8) = 512 CTAs.
// ---------------------------------------------------------------------------
#define GRU_STAGE_F 6400

__global__ __launch_bounds__(256, 3) void gru_mma_kernel(
    const float* __restrict__ x, int xs_stride,
    const float* __restrict__ h, int hs_stride,
    const float* __restrict__ kmat, const float* __restrict__ rkmat,
    const float* __restrict__ bias,
    float* __restrict__ out, int out_stride,
    const float* __restrict__ xin,
    float* __restrict__ cout)
{
    extern __shared__ float smem_dyn[];
    uint32_t smem_u = (uint32_t)__cvta_generic_to_shared(smem_dyn);

    int tid = threadIdx.x;
    int lane = tid & 31;
    int wid = tid >> 5;
    int warp_m = wid & 3;       // m offset warp_m*16
    int warp_n = wid >> 2;      // n offset warp_n*16
    int bm0 = blockIdx.x * 64;
    int bn0 = blockIdx.y * 32;
    int g4 = lane >> 2;
    int t4 = lane & 3;

    float acc[4][2][4];
    #pragma unroll
    for (int s = 0; s < 4; s++)
        #pragma unroll
        for (int ni = 0; ni < 2; ni++)
            #pragma unroll
            for (int j = 0; j < 4; j++)
                acc[s][ni][j] = 0.f;

    // X/H staging via cp.async: 2 CP16 per thread (64 rows x 4 quads x2)
    auto stageXH = [&](int p, int kt0) {
        uint32_t su = smem_u + (uint32_t)(p * GRU_STAGE_F) * 4u;
        #pragma unroll
        for (int it = 0; it < 2; it++) {
            int idx = tid + it * 256;       // 0..511
            if (idx < 256) {
                int row = idx >> 2, q = idx & 3;
                const float* src = x + (size_t)(bm0 + row) * xs_stride + kt0 + q * 4;
                CP16(su + (uint32_t)(row * 20 + q * 4) * 4u, src);
            } else {
                int j = idx - 256;
                int row = j >> 2, q = j & 3;
                const float* src = h + (size_t)(bm0 + row) * hs_stride + kt0 + q * 4;
                CP16(su + (uint32_t)(1280 + row * 20 + q * 4) * 4u, src);
            }
        }
    };

    // W staging: LDG into regs (prefetch), STS transposed [m][n][k] stride 20.
    float4 wreg[3];
    auto ldgW = [&](int kt0) {
        #pragma unroll
        for (int it = 0; it < 3; it++) {
            int idx = tid + it * 256;       // 0..767
            int m = idx >> 7, rem = idx & 127;
            int kk = rem >> 3, nq = rem & 7;
            const float* src = (m < 3) ? kmat : rkmat;
            int pp = (m < 3) ? m : (m - 3);
            wreg[it] = *(const float4*)(src + (size_t)(kt0 + kk) * 768
                                        + pp * 256 + bn0 + nq * 4);
        }
    };
    auto stsW = [&](int p) {
        float* wb = smem_dyn + p * GRU_STAGE_F + 2560;
        #pragma unroll
        for (int it = 0; it < 3; it++) {
            int idx = tid + it * 256;
            int m = idx >> 7, rem = idx & 127;
            int kk = rem >> 3, nq = rem & 7;
            float* d = wb + (m * 32 + nq * 4) * 20 + kk;
            d[0]  = wreg[it].x;
            d[20] = wreg[it].y;
            d[40] = wreg[it].z;
            d[60] = wreg[it].w;
        }
    };

    // ldmatrix lane offsets (bytes)
    uint32_t aoff = (uint32_t)((lane & 15) * 80 + (lane >> 4) * 16);
    uint32_t boff = (uint32_t)(((lane & 7) + ((lane & 16) >> 1)) * 80
                               + ((lane >> 3) & 1) * 16);

    ldgW(0);
    stageXH(0, 0);
    CP_COMMIT();
    stsW(0);

    for (int t = 0; t < 16; t++) {
        if (t < 15) { ldgW((t + 1) * 16); stageXH((t + 1) & 1, (t + 1) * 16); }
        CP_COMMIT();
        CP_WAIT1();
        __syncthreads();

        uint32_t pbase = (t & 1) ? (uint32_t)(GRU_STAGE_F * 4) : 0u;
        uint32_t xb = smem_u + pbase + (uint32_t)(warp_m * 1280) + aoff;  // 16 rows*80B
        uint32_t hb = smem_u + pbase + 5120u + (uint32_t)(warp_m * 1280) + aoff;
        uint32_t wb = smem_u + pbase + 10240u + (uint32_t)(warp_n * 1280) + boff;

        #pragma unroll
        for (int ks = 0; ks < 2; ks++) {
            uint32_t ko = (uint32_t)(ks * 32);   // 8 floats
            uint32_t ax[4], ah[4];
            LDSM4(ax[0], ax[1], ax[2], ax[3], xb + ko);
            LDSM4(ah[0], ah[1], ah[2], ah[3], hb + ko);
            #pragma unroll
            for (int m = 0; m < 6; m++) {
                const int set = (m == 0 || m == 3) ? 0 : (m == 1 || m == 4) ? 1 : (m == 2) ? 2 : 3;
                uint32_t bf0, bf1, bf2, bf3;
                LDSM4(bf0, bf1, bf2, bf3, wb + (uint32_t)(m * 2560) + ko);
                if (m < 3) {
                    MMA_TF32(acc[set][0], ax, bf0, bf1);
                    MMA_TF32(acc[set][1], ax, bf2, bf3);
                } else {
                    MMA_TF32(acc[set][0], ah, bf0, bf1);
                    MMA_TF32(acc[set][1], ah, bf2, bf3);
                }
            }
        }
        __syncthreads();
        if (t < 15) stsW((t + 1) & 1);
    }

    // epilogue: gate math
    #pragma unroll
    for (int ni = 0; ni < 2; ni++) {
        int colg = bn0 + warp_n * 16 + ni * 8 + 2 * t4;
        #pragma unroll
        for (int half = 0; half < 2; half++) {
            int row = bm0 + warp_m * 16 + g4 + half * 8;
            float2 hv = *(const float2*)&h[(size_t)row * hs_stride + colg];
            float o2[2];
            #pragma unroll
            for (int j = 0; j < 2; j++) {
                int col = colg + j;
                int ri = half * 2 + j;
                float az  = acc[0][ni][ri] + bias[col]       + bias[768 + col];
                float ar  = acc[1][ni][ri] + bias[256 + col] + bias[1024 + col];
                float axh = acc[2][ni][ri] + bias[512 + col];
                float ahh = acc[3][ni][ri] + bias[1280 + col];
                float z  = 1.f / (1.f + __expf(-az));
                float rg = 1.f / (1.f + __expf(-ar));
                float cand = tanhf(axh + rg * ahh);
                float hvv = j ? hv.y : hv.x;
                o2[j] = z * hvv + (1.f - z) * cand;
            }
            *(float2*)&out[(size_t)row * out_stride + colg] = make_float2(o2[0], o2[1]);
            if (cout) {
                float2 xi = *(const float2*)&xin[(size_t)row * HID + colg];
                *(float2*)&cout[(size_t)row * HID + colg] =
                    make_float2(o2[0] + xi.x, o2[1] + xi.y);
            }
        }
    }
}

// ---------------------------------------------------------------------------
// Tail v3 (R5, 75us): smem-staged, fused new_buf write. Block = 32 b x 8 f.
// ---------------------------------------------------------------------------
#define T_ROW4 41
#define T_STAGE4 (32 * T_ROW4)

__global__ __launch_bounds__(256, 2) void tail_kernel(
    const float* __restrict__ buf, const float* __restrict__ c0,
    const float* __restrict__ c,
    const float* __restrict__ w_out, const float* __restrict__ conv_w,
    const float* __restrict__ pw_w,
    const float* __restrict__ bn_gamma, const float* __restrict__ bn_beta,
    const float* __restrict__ bn_mean, const float* __restrict__ bn_var,
    float* __restrict__ coefs, float* __restrict__ new_buf)
{
    __shared__ float4 sT[2][T_STAGE4];
    __shared__ float  sC[32][68];
    __shared__ float  s_cw[KT * 8 * OC];
    __shared__ float  s_pw[OC * OC];
    __shared__ float  s_scale[OC], s_shift[OC];
    __shared__ float  s_wo[8][325];

    uint32_t sT_u = (uint32_t)__cvta_generic_to_shared(&sT[0][0]);

    int tid = threadIdx.x;
    int f0 = blockIdx.x * 8;
    int b0 = blockIdx.y * 32;
    int bi = tid >> 3;
    int fi = tid & 7;
    int f = f0 + fi;
    int b = b0 + bi;
    int g = f / 12;
    int gmin = f0 / 12;

    auto stage = [&](int t, int p) {
        #pragma unroll
        for (int it = 0; it < 4; it++) {
            int i = tid + it * 256;
            int row = i >> 5, col4 = i & 31;
            const float* src = (t < 4)
                ? buf + (size_t)(b0 + row) * 6144 + t * 1536 + f0 * 16 + col4 * 4
                : c0  + (size_t)(b0 + row) * 1536 + f0 * 16 + col4 * 4;
            uint32_t dst = sT_u + (uint32_t)(p * T_STAGE4 + row * T_ROW4
                                             + (col4 >> 2) * 5 + (col4 & 3)) * 16u;
            CP16(dst, src);
        }
    };

    stage(0, 0);
    CP_COMMIT();

    for (int idx = tid; idx < KT * 8 * OC; idx += 256) s_cw[idx] = conv_w[idx];
    for (int idx = tid; idx < OC * OC; idx += 256)     s_pw[idx] = pw_w[idx];
    if (tid < OC) {
        float inv = rsqrtf(bn_var[tid] + 1e-3f);
        float sc = inv * bn_gamma[tid];
        s_scale[tid] = sc;
        s_shift[tid] = bn_beta[tid] - bn_mean[tid] * sc;
    }
    for (int idx = tid; idx < 8 * 320; idx += 256) {
        int ff = idx / 320;
        int rem = idx - ff * 320;
        int i = rem / 10, o = rem - i * 10;
        int fg = f0 + ff;
        int gg = fg / 12;
        int oo0 = (fg * 10) % 120;
        s_wo[ff][rem] = w_out[gg * 3840 + i * 120 + oo0 + o];
    }
    for (int i = tid; i < 512; i += 256) {
        int row = i >> 4, col4 = i & 15;
        int jh = col4 >> 3;
        int gj = gmin + jh; if (gj > 7) gj = 7;
        const float4 v = *(const float4*)&c[(size_t)(b0 + row) * HID
                                            + gj * 32 + (col4 & 7) * 4];
        *(float4*)&sC[row][col4 * 4] = v;
    }

    float y[OC];
    #pragma unroll
    for (int o = 0; o < OC; o++) y[o] = 0.f;

    #pragma unroll
    for (int t = 0; t < KT; t++) {
        if (t < KT - 1) stage(t + 1, (t + 1) & 1);
        CP_COMMIT();
        CP_WAIT1();
        __syncthreads();

        const float* st = (const float*)&sT[t & 1][0];
        int base = bi * 164 + fi * 20;
        float v[16];
        #pragma unroll
        for (int q = 0; q < 4; q++) {
            float4 w4 = *(const float4*)&st[base + q * 4];
            v[q*4+0] = w4.x; v[q*4+1] = w4.y; v[q*4+2] = w4.z; v[q*4+3] = w4.w;
        }
        #pragma unroll
        for (int g2 = 0; g2 < 2; g2++)
            #pragma unroll
            for (int i = 0; i < 8; i++) {
                float xv = v[g2 * 8 + i];
                #pragma unroll
                for (int o5 = 0; o5 < 5; o5++)
                    y[g2 * 5 + o5] = fmaf(xv, s_cw[t * 80 + i * OC + g2 * 5 + o5],
                                          y[g2 * 5 + o5]);
            }
        if (t >= 1) {
            #pragma unroll
            for (int it = 0; it < 4; it++) {
                int i = tid + it * 256;
                int row = i >> 5, col4 = i & 31;
                float4 w4 = sT[t & 1][row * T_ROW4 + (col4 >> 2) * 5 + (col4 & 3)];
                *(float4*)&new_buf[(size_t)(b0 + row) * 6144 + (t - 1) * 1536
                                   + f0 * 16 + col4 * 4] = w4;
            }
        }
        __syncthreads();
    }

    float c0o[OC];
    #pragma unroll
    for (int o = 0; o < OC; o++) {
        float a = 0.f;
        #pragma unroll
        for (int k = 0; k < OC; k++) a = fmaf(y[k], s_pw[k * OC + o], a);
        c0o[o] = fmaxf(a * s_scale[o] + s_shift[o], 0.f);
    }

    int goff = (g - gmin) * 32;
    float cr[32];
    #pragma unroll
    for (int q = 0; q < 8; q++) {
        float4 vv = *(const float4*)&sC[bi][goff + q * 4];
        cr[q*4+0] = vv.x; cr[q*4+1] = vv.y; cr[q*4+2] = vv.z; cr[q*4+3] = vv.w;
    }
    float* cf = coefs + (size_t)b * 960 + f * 2;
    #pragma unroll
    for (int j = 0; j < 5; j++) {
        float a0 = 0.f, a1 = 0.f;
        #pragma unroll
        for (int i = 0; i < 32; i++) {
            a0 = fmaf(cr[i], s_wo[fi][i * 10 + 2 * j], a0);
            a1 = fmaf(cr[i], s_wo[fi][i * 10 + 2 * j + 1], a1);
        }
        float2 o2 = make_float2(tanhf(a0) + c0o[2 * j], tanhf(a1) + c0o[2 * j + 1]);
        *(float2*)&cf[j * 192] = o2;
    }
}

// ---------------------------------------------------------------------------
__global__ __launch_bounds__(256) void alpha_kernel(
    const float* __restrict__ c, const float* __restrict__ faw,
    const float* __restrict__ fab, float* __restrict__ alpha)
{
    int b = blockIdx.x * 8 + (threadIdx.x >> 5);
    int lane = threadIdx.x & 31;
    float s = 0.f;
    #pragma unroll
    for (int k = 0; k < 8; k++)
        s = fmaf(c[(size_t)b * HID + k * 32 + lane], faw[k * 32 + lane], s);
    #pragma unroll
    for (int off = 16; off; off >>= 1)
        s += __shfl_xor_sync(0xFFFFFFFFu, s, off);
    if (lane == 0)
        alpha[b] = 1.f / (1.f + expf(-(s + fab[0])));
}

// ---------------------------------------------------------------------------
extern "C" void kernel_launch(void* const* d_in, const int* in_sizes, int n_in,
                              void* d_out, int out_size)
{
    const float* emb      = (const float*)d_in[0];
    const float* c0       = (const float*)d_in[1];
    const float* state    = (const float*)d_in[2];
    const float* convbuf  = (const float*)d_in[3];
    const float* w_in     = (const float*)d_in[4];
    const float* k0       = (const float*)d_in[5];
    const float* rk0      = (const float*)d_in[6];
    const float* b0       = (const float*)d_in[7];
    const float* k1       = (const float*)d_in[8];
    const float* rk1      = (const float*)d_in[9];
    const float* b1       = (const float*)d_in[10];
    const float* w_out    = (const float*)d_in[11];
    const float* faw      = (const float*)d_in[12];
    const float* fab      = (const float*)d_in[13];
    const float* conv_w   = (const float*)d_in[14];
    const float* pw_w     = (const float*)d_in[15];
    const float* bn_gamma = (const float*)d_in[16];
    const float* bn_beta  = (const float*)d_in[17];
    const float* bn_mean  = (const float*)d_in[18];
    const float* bn_var   = (const float*)d_in[19];

    float* out = (float*)d_out;
    float* xin; float* cbuf;
    cudaGetSymbolAddress((void**)&xin,  g_xin);
    cudaGetSymbolAddress((void**)&cbuf, g_c);

    const int gru_smem = 2 * GRU_STAGE_F * 4;   // 51,200 B
    cudaFuncSetAttribute(gru_mma_kernel,
        cudaFuncAttributeMaxDynamicSharedMemorySize, gru_smem);

    xin_kernel<<<BATCH / 8, 256>>>(emb, w_in, xin);

    gru_mma_kernel<<<dim3(BATCH / 64, HID / 32), 256, gru_smem>>>(
        xin, HID, state, 2 * HID, k0, rk0, b0,
        out + OFF_STATE, 2 * HID, nullptr, nullptr);

    gru_mma_kernel<<<dim3(BATCH / 64, HID / 32), 256, gru_smem>>>(
        out + OFF_STATE, 2 * HID, state + HID, 2 * HID, k1, rk1, b1,
        out + OFF_STATE + HID, 2 * HID, xin, cbuf);

    tail_kernel<<<dim3(FREQ / 8, BATCH / 32), 256>>>(
        convbuf, c0, cbuf, w_out, conv_w, pw_w,
        bn_gamma, bn_beta, bn_mean, bn_var,
        out + OFF_COEFS, out + OFF_BUF);

    alpha_kernel<<<BATCH / 8, 256>>>(cbuf, faw, fab, out + OFF_ALPHA);
}

// round 11
// speedup vs baseline: 1.2358x; 1.2358x over previous
#include <cuda_runtime.h>
#include <cuda_bf16.h>
#include <math.h>
#include <stdint.h>

#define BATCH 4096
#define EMB 256
#define HID 256
#define FREQ 96
#define CHAN 16
#define OC 10
#define KT 5

#define OFF_COEFS 0
#define N_COEFS   (BATCH * 5 * 96 * 2)
#define OFF_ALPHA (N_COEFS)
#define N_ALPHA   (BATCH)
#define OFF_STATE (OFF_ALPHA + N_ALPHA)
#define N_STATE   (BATCH * 2 * HID)
#define OFF_BUF   (OFF_STATE + N_STATE)
#define N_BUF     (BATCH * 4 * FREQ * CHAN)

__device__ float g_xin[BATCH * HID];
__device__ float g_c[BATCH * HID];

#define MMA_TF32(d, a, b) \
  asm volatile("mma.sync.aligned.m16n8k8.row.col.f32.tf32.tf32.f32 " \
      "{%0,%1,%2,%3}, {%4,%5,%6,%7}, {%8,%9}, {%0,%1,%2,%3};" \
      : "+f"((d)[0]), "+f"((d)[1]), "+f"((d)[2]), "+f"((d)[3]) \
      : "r"((a)[0]), "r"((a)[1]), "r"((a)[2]), "r"((a)[3]), \
        "r"((b)[0]), "r"((b)[1]))

#define CP16(dst_u32, src_ptr) \
  asm volatile("cp.async.ca.shared.global [%0], [%1], 16;" :: "r"(dst_u32), "l"(src_ptr))
#define CP_COMMIT() asm volatile("cp.async.commit_group;")
#define CP_WAIT1()  asm volatile("cp.async.wait_group 1;")

// ---------------------------------------------------------------------------
// x_in = relu(grouped_linear(emb, w_in))
// ---------------------------------------------------------------------------
__global__ __launch_bounds__(256) void xin_kernel(
    const float* __restrict__ emb, const float* __restrict__ w_in,
    float* __restrict__ xout)
{
    __shared__ float sE[8][EMB];
    int b0 = blockIdx.x * 8;
    int tid = threadIdx.x;
    for (int idx = tid; idx < 8 * EMB; idx += 256) {
        int r = idx >> 8, col = idx & 255;
        sE[r][col] = emb[(b0 + r) * EMB + col];
    }
    __syncthreads();
    int j = tid;
    int g = j >> 5, jo = j & 31;
    float acc[8] = {0.f,0.f,0.f,0.f,0.f,0.f,0.f,0.f};
    const float* w = w_in + g * (32 * 32) + jo;
    #pragma unroll 8
    for (int i = 0; i < 32; i++) {
        float wv = w[i * 32];
        #pragma unroll
        for (int r = 0; r < 8; r++)
            acc[r] = fmaf(sE[r][(g << 5) + i], wv, acc[r]);
    }
    #pragma unroll
    for (int r = 0; r < 8; r++)
        xout[(b0 + r) * HID + j] = fmaxf(acc[r], 0.f);
}

// ---------------------------------------------------------------------------
// Fused GRU cell, tf32 mma.sync, cp.async double-buffered (R5 version,
// measured best: ~36us each). CTA 128x32, 8 warps = 4m x 2n.
// ---------------------------------------------------------------------------
#define GRU_STAGE_F 8960

__global__ __launch_bounds__(256) void gru_mma_kernel(
    const float* __restrict__ x, int xs_stride,
    const float* __restrict__ h, int hs_stride,
    const float* __restrict__ kmat, const float* __restrict__ rkmat,
    const float* __restrict__ bias,
    float* __restrict__ out, int out_stride,
    const float* __restrict__ xin,
    float* __restrict__ cout)
{
    extern __shared__ float smem_dyn[];
    uint32_t smem_u = (uint32_t)__cvta_generic_to_shared(smem_dyn);

    int tid = threadIdx.x;
    int lane = tid & 31;
    int wid = tid >> 5;
    int warp_m = wid & 3;
    int warp_n = wid >> 2;
    int bm0 = blockIdx.x * 128;
    int bn0 = blockIdx.y * 32;
    int g4 = lane >> 2;
    int t4 = lane & 3;

    float acc[4][2][2][4];
    #pragma unroll
    for (int s = 0; s < 4; s++)
        #pragma unroll
        for (int mi = 0; mi < 2; mi++)
            #pragma unroll
            for (int ni = 0; ni < 2; ni++)
                #pragma unroll
                for (int j = 0; j < 4; j++)
                    acc[s][mi][ni][j] = 0.f;

    auto stage = [&](int p, int kt0) {
        uint32_t su = smem_u + (uint32_t)(p * GRU_STAGE_F) * 4u;
        #pragma unroll
        for (int it = 0; it < 7; it++) {
            int idx = tid + it * 256;
            if (idx < 512) {
                int row = idx >> 2, q = idx & 3;
                const float* src = x + (size_t)(bm0 + row) * xs_stride + kt0 + q * 4;
                CP16(su + (uint32_t)(row * 20 + q * 4) * 4u, src);
            } else if (idx < 1024) {
                int j = idx - 512;
                int row = j >> 2, q = j & 3;
                const float* src = h + (size_t)(bm0 + row) * hs_stride + kt0 + q * 4;
                CP16(su + (uint32_t)(2560 + row * 20 + q * 4) * 4u, src);
            } else {
                int w = idx - 1024;
                int m = w >> 7;
                int rem = w & 127;
                int kk = rem >> 3, q = rem & 7;
                const float* sw = (m < 3) ? kmat : rkmat;
                int pp = (m < 3) ? m : (m - 3);
                const float* src = sw + (size_t)(kt0 + kk) * 768 + pp * 256 + bn0 + q * 4;
                CP16(su + (uint32_t)(5120 + (m * 16 + kk) * 40 + q * 4) * 4u, src);
            }
        }
    };

    stage(0, 0);
    CP_COMMIT();

    for (int t = 0; t < 16; t++) {
        if (t < 15) stage((t + 1) & 1, (t + 1) * 16);
        CP_COMMIT();
        CP_WAIT1();
        __syncthreads();

        const float* bufp = smem_dyn + (t & 1) * GRU_STAGE_F;
        const float* sXf = bufp;
        const float* sHf = bufp + 2560;
        const float* sWf = bufp + 5120;

        #pragma unroll
        for (int ks = 0; ks < 16; ks += 8) {
            uint32_t ax[2][4], ah[2][4];
            #pragma unroll
            for (int mi = 0; mi < 2; mi++) {
                int r = warp_m * 32 + mi * 16 + g4;
                ax[mi][0] = __float_as_uint(sXf[r * 20 + ks + t4]);
                ax[mi][1] = __float_as_uint(sXf[(r + 8) * 20 + ks + t4]);
                ax[mi][2] = __float_as_uint(sXf[r * 20 + ks + t4 + 4]);
                ax[mi][3] = __float_as_uint(sXf[(r + 8) * 20 + ks + t4 + 4]);
                ah[mi][0] = __float_as_uint(sHf[r * 20 + ks + t4]);
                ah[mi][1] = __float_as_uint(sHf[(r + 8) * 20 + ks + t4]);
                ah[mi][2] = __float_as_uint(sHf[r * 20 + ks + t4 + 4]);
                ah[mi][3] = __float_as_uint(sHf[(r + 8) * 20 + ks + t4 + 4]);
            }
            #pragma unroll
            for (int m = 0; m < 6; m++) {
                const int set = (m == 0 || m == 3) ? 0 : (m == 1 || m == 4) ? 1 : (m == 2) ? 2 : 3;
                uint32_t bf[2][2];
                #pragma unroll
                for (int ni = 0; ni < 2; ni++) {
                    int n = warp_n * 16 + ni * 8 + g4;
                    bf[ni][0] = __float_as_uint(sWf[(m * 16 + ks + t4) * 40 + n]);
                    bf[ni][1] = __float_as_uint(sWf[(m * 16 + ks + t4 + 4) * 40 + n]);
                }
                #pragma unroll
                for (int mi = 0; mi < 2; mi++)
                    #pragma unroll
                    for (int ni = 0; ni < 2; ni++) {
                        if (m < 3) { MMA_TF32(acc[set][mi][ni], ax[mi], bf[ni]); }
                        else       { MMA_TF32(acc[set][mi][ni], ah[mi], bf[ni]); }
                    }
            }
        }
        __syncthreads();
    }

    #pragma unroll
    for (int mi = 0; mi < 2; mi++) {
        #pragma unroll
        for (int ni = 0; ni < 2; ni++) {
            int colg = bn0 + warp_n * 16 + ni * 8 + 2 * t4;
            #pragma unroll
            for (int half = 0; half < 2; half++) {
                int row = bm0 + warp_m * 32 + mi * 16 + g4 + half * 8;
                float2 hv = *(const float2*)&h[(size_t)row * hs_stride + colg];
                float o2[2];
                #pragma unroll
                for (int j = 0; j < 2; j++) {
                    int col = colg + j;
                    int ri = half * 2 + j;
                    float az  = acc[0][mi][ni][ri] + bias[col]       + bias[768 + col];
                    float ar  = acc[1][mi][ni][ri] + bias[256 + col] + bias[1024 + col];
                    float axh = acc[2][mi][ni][ri] + bias[512 + col];
                    float ahh = acc[3][mi][ni][ri] + bias[1280 + col];
                    float z  = 1.f / (1.f + __expf(-az));
                    float rg = 1.f / (1.f + __expf(-ar));
                    float cand = tanhf(axh + rg * ahh);
                    float hvv = j ? hv.y : hv.x;
                    o2[j] = z * hvv + (1.f - z) * cand;
                }
                *(float2*)&out[(size_t)row * out_stride + colg] = make_float2(o2[0], o2[1]);
                if (cout) {
                    float2 xi = *(const float2*)&xin[(size_t)row * HID + colg];
                    *(float2*)&cout[(size_t)row * HID + colg] =
                        make_float2(o2[0] + xi.x, o2[1] + xi.y);
                }
            }
        }
    }
}

// ---------------------------------------------------------------------------
// Tail v6: fused new_buf write (R5 algorithm) + register-slim body (R6 style).
// Block = 32 b x 8 f, __launch_bounds__(256,3) -> target 3 CTAs/SM.
// ---------------------------------------------------------------------------
#define T_ROW4 41
#define T_STAGE4 (32 * T_ROW4)

__global__ __launch_bounds__(256, 3) void tail_kernel(
    const float* __restrict__ buf, const float* __restrict__ c0,
    const float* __restrict__ c,
    const float* __restrict__ w_out, const float* __restrict__ conv_w,
    const float* __restrict__ pw_w,
    const float* __restrict__ bn_gamma, const float* __restrict__ bn_beta,
    const float* __restrict__ bn_mean, const float* __restrict__ bn_var,
    float* __restrict__ coefs, float* __restrict__ new_buf)
{
    __shared__ float4 sT[2][T_STAGE4];
    __shared__ float  sC[32][68];
    __shared__ float  s_cw[KT * 8 * OC];
    __shared__ float  s_pw[OC * OC];
    __shared__ float  s_scale[OC], s_shift[OC];
    __shared__ float  s_wo[8][325];

    uint32_t sT_u = (uint32_t)__cvta_generic_to_shared(&sT[0][0]);

    int tid = threadIdx.x;
    int f0 = blockIdx.x * 8;
    int b0 = blockIdx.y * 32;
    int bi = tid >> 3;
    int fi = tid & 7;
    int f = f0 + fi;
    int b = b0 + bi;
    int g = f / 12;
    int gmin = f0 / 12;

    auto stage = [&](int t, int p) {
        #pragma unroll
        for (int it = 0; it < 4; it++) {
            int i = tid + it * 256;
            int row = i >> 5, col4 = i & 31;
            const float* src = (t < 4)
                ? buf + (size_t)(b0 + row) * 6144 + t * 1536 + f0 * 16 + col4 * 4
                : c0  + (size_t)(b0 + row) * 1536 + f0 * 16 + col4 * 4;
            uint32_t dst = sT_u + (uint32_t)(p * T_STAGE4 + row * T_ROW4
                                             + (col4 >> 2) * 5 + (col4 & 3)) * 16u;
            CP16(dst, src);
        }
    };

    stage(0, 0);
    CP_COMMIT();

    for (int idx = tid; idx < KT * 8 * OC; idx += 256) s_cw[idx] = conv_w[idx];
    for (int idx = tid; idx < OC * OC; idx += 256)     s_pw[idx] = pw_w[idx];
    if (tid < OC) {
        float inv = rsqrtf(bn_var[tid] + 1e-3f);
        float sc = inv * bn_gamma[tid];
        s_scale[tid] = sc;
        s_shift[tid] = bn_beta[tid] - bn_mean[tid] * sc;
    }
    for (int idx = tid; idx < 8 * 320; idx += 256) {
        int ff = idx / 320;
        int rem = idx - ff * 320;
        int i = rem / 10, o = rem - i * 10;
        int fg = f0 + ff;
        int gg = fg / 12;
        int oo0 = (fg * 10) % 120;
        s_wo[ff][rem] = w_out[gg * 3840 + i * 120 + oo0 + o];
    }
    for (int i = tid; i < 512; i += 256) {
        int row = i >> 4, col4 = i & 15;
        int jh = col4 >> 3;
        int gj = gmin + jh; if (gj > 7) gj = 7;
        const float4 v = *(const float4*)&c[(size_t)(b0 + row) * HID
                                            + gj * 32 + (col4 & 7) * 4];
        *(float4*)&sC[row][col4 * 4] = v;
    }

    float y[OC];
    #pragma unroll
    for (int o = 0; o < OC; o++) y[o] = 0.f;

    #pragma unroll
    for (int t = 0; t < KT; t++) {
        if (t < KT - 1) stage(t + 1, (t + 1) & 1);
        CP_COMMIT();
        CP_WAIT1();
        __syncthreads();

        // conv: consume staged float4 directly (no v[16] buffer)
        const float* st = (const float*)&sT[t & 1][0];
        int base = bi * 164 + fi * 20;
        #pragma unroll
        for (int q = 0; q < 4; q++) {
            float4 w4 = *(const float4*)&st[base + q * 4];
            int g2 = q >> 1;
            int i0 = (q & 1) * 4;
            const float* cw = &s_cw[t * 80 + i0 * OC + g2 * 5];
            #pragma unroll
            for (int o5 = 0; o5 < 5; o5++) {
                float acc = y[g2 * 5 + o5];
                acc = fmaf(w4.x, cw[0 * OC + o5], acc);
                acc = fmaf(w4.y, cw[1 * OC + o5], acc);
                acc = fmaf(w4.z, cw[2 * OC + o5], acc);
                acc = fmaf(w4.w, cw[3 * OC + o5], acc);
                y[g2 * 5 + o5] = acc;
            }
        }
        // fused new_buf write (coalesced, from smem)
        if (t >= 1) {
            #pragma unroll
            for (int it = 0; it < 4; it++) {
                int i = tid + it * 256;
                int row = i >> 5, col4 = i & 31;
                float4 w4 = sT[t & 1][row * T_ROW4 + (col4 >> 2) * 5 + (col4 & 3)];
                *(float4*)&new_buf[(size_t)(b0 + row) * 6144 + (t - 1) * 1536
                                   + f0 * 16 + col4 * 4] = w4;
            }
        }
        __syncthreads();
    }

    // pointwise + BN + relu
    float a[OC];
    #pragma unroll
    for (int o = 0; o < OC; o++) {
        float s = 0.f;
        #pragma unroll
        for (int k = 0; k < OC; k++) s = fmaf(y[k], s_pw[k * OC + o], s);
        a[o] = fmaxf(s * s_scale[o] + s_shift[o], 0.f);
    }

    // grouped out-projection directly from sC (i-outer, no cr[32])
    int goff = (g - gmin) * 32;
    float p[OC];
    #pragma unroll
    for (int o = 0; o < OC; o++) p[o] = 0.f;
    #pragma unroll
    for (int i = 0; i < 32; i++) {
        float cv = sC[bi][goff + i];
        #pragma unroll
        for (int o = 0; o < OC; o++)
            p[o] = fmaf(cv, s_wo[fi][i * 10 + o], p[o]);
    }
    float* cf = coefs + (size_t)b * 960 + f * 2;
    #pragma unroll
    for (int j = 0; j < 5; j++) {
        float2 o2 = make_float2(tanhf(p[2 * j]) + a[2 * j],
                                tanhf(p[2 * j + 1]) + a[2 * j + 1]);
        *(float2*)&cf[j * 192] = o2;
    }
}

// ---------------------------------------------------------------------------
__global__ __launch_bounds__(256) void alpha_kernel(
    const float* __restrict__ c, const float* __restrict__ faw,
    const float* __restrict__ fab, float* __restrict__ alpha)
{
    int b = blockIdx.x * 8 + (threadIdx.x >> 5);
    int lane = threadIdx.x & 31;
    float s = 0.f;
    #pragma unroll
    for (int k = 0; k < 8; k++)
        s = fmaf(c[(size_t)b * HID + k * 32 + lane], faw[k * 32 + lane], s);
    #pragma unroll
    for (int off = 16; off; off >>= 1)
        s += __shfl_xor_sync(0xFFFFFFFFu, s, off);
    if (lane == 0)
        alpha[b] = 1.f / (1.f + expf(-(s + fab[0])));
}

// ---------------------------------------------------------------------------
extern "C" void kernel_launch(void* const* d_in, const int* in_sizes, int n_in,
                              void* d_out, int out_size)
{
    const float* emb      = (const float*)d_in[0];
    const float* c0       = (const float*)d_in[1];
    const float* state    = (const float*)d_in[2];
    const float* convbuf  = (const float*)d_in[3];
    const float* w_in     = (const float*)d_in[4];
    const float* k0       = (const float*)d_in[5];
    const float* rk0      = (const float*)d_in[6];
    const float* b0       = (const float*)d_in[7];
    const float* k1       = (const float*)d_in[8];
    const float* rk1      = (const float*)d_in[9];
    const float* b1       = (const float*)d_in[10];
    const float* w_out    = (const float*)d_in[11];
    const float* faw      = (const float*)d_in[12];
    const float* fab      = (const float*)d_in[13];
    const float* conv_w   = (const float*)d_in[14];
    const float* pw_w     = (const float*)d_in[15];
    const float* bn_gamma = (const float*)d_in[16];
    const float* bn_beta  = (const float*)d_in[17];
    const float* bn_mean  = (const float*)d_in[18];
    const float* bn_var   = (const float*)d_in[19];

    float* out = (float*)d_out;
    float* xin; float* cbuf;
    cudaGetSymbolAddress((void**)&xin,  g_xin);
    cudaGetSymbolAddress((void**)&cbuf, g_c);

    const int gru_smem = 2 * GRU_STAGE_F * 4;   // 71,680 B
    cudaFuncSetAttribute(gru_mma_kernel,
        cudaFuncAttributeMaxDynamicSharedMemorySize, gru_smem);

    xin_kernel<<<BATCH / 8, 256>>>(emb, w_in, xin);

    gru_mma_kernel<<<dim3(BATCH / 128, HID / 32), 256, gru_smem>>>(
        xin, HID, state, 2 * HID, k0, rk0, b0,
        out + OFF_STATE, 2 * HID, nullptr, nullptr);

    gru_mma_kernel<<<dim3(BATCH / 128, HID / 32), 256, gru_smem>>>(
        out + OFF_STATE, 2 * HID, state + HID, 2 * HID, k1, rk1, b1,
        out + OFF_STATE + HID, 2 * HID, xin, cbuf);

    tail_kernel<<<dim3(FREQ / 8, BATCH / 32), 256>>>(
        convbuf, c0, cbuf, w_out, conv_w, pw_w,
        bn_gamma, bn_beta, bn_mean, bn_var,
        out + OFF_COEFS, out + OFF_BUF);

    alpha_kernel<<<BATCH / 8, 256>>>(cbuf, faw, fab, out + OFF_ALPHA);
}